// round 1
// baseline (speedup 1.0000x reference)
#include <cuda_runtime.h>
#include <cuda_bf16.h>

// INT4 symmetric grouped dequant:
//   packed: TOTAL/2 int32, each in [0,256): low nibble = even element, high = odd
//   scale:  (OUT, GROUPS, 1) fp32
//   out:    (OUT, GROUPS*GSIZE) fp32, out[i] = (nibble - 8) * scale[i / GSIZE]
//
// Shapes: OUT=4096, GROUPS=86, GSIZE=128 -> TOTAL = 45,088,768
// Each thread: 1x int4 load (4 packed -> 8 codes), 2x float4 store.
// Thread t covers output [8t, 8t+8); group = 8t/128 = t>>4 (8*16=128 exact).

#define N_PACKED   22544384   // TOTAL/2
#define N_THREADS  (N_PACKED / 4)   // 5,636,096

__global__ void __launch_bounds__(256)
int4_dequant_kernel(const int4* __restrict__ packed,
                    const float* __restrict__ scale,
                    float4* __restrict__ out)
{
    const int t = blockIdx.x * blockDim.x + threadIdx.x;
    // exact grid: no bounds check needed, but keep it cheap and safe
    if (t >= N_THREADS) return;

    const int4 p = packed[t];
    const float s = __ldg(&scale[t >> 4]);

    float4 a, b;
    a.x = (float)((p.x & 15) - 8) * s;
    a.y = (float)(((p.x >> 4) & 15) - 8) * s;
    a.z = (float)((p.y & 15) - 8) * s;
    a.w = (float)(((p.y >> 4) & 15) - 8) * s;
    b.x = (float)((p.z & 15) - 8) * s;
    b.y = (float)(((p.z >> 4) & 15) - 8) * s;
    b.z = (float)((p.w & 15) - 8) * s;
    b.w = (float)(((p.w >> 4) & 15) - 8) * s;

    out[2 * t]     = a;
    out[2 * t + 1] = b;
}

extern "C" void kernel_launch(void* const* d_in, const int* in_sizes, int n_in,
                              void* d_out, int out_size)
{
    const int4*  packed = (const int4*)d_in[0];   // int32 array, 16B-vectorized
    const float* scale  = (const float*)d_in[1];
    float4*      out    = (float4*)d_out;

    const int threads = 256;
    const int blocks  = (N_THREADS + threads - 1) / threads;  // 22,016 exact
    int4_dequant_kernel<<<blocks, threads>>>(packed, scale, out);
}